// round 14
// baseline (speedup 1.0000x reference)
#include <cuda_runtime.h>

#define NU   100000
#define NI   100000
#define N2   200000            // total output rows (users + items)
#define NNZV 3200000
#define D    128
#define NBLK 196               // ceil(N2/1024)

// ---- static scratch (no allocations allowed) ----
__device__ int  g_cnt[N2];
__device__ int  g_off[N2];     // block-LOCAL exclusive offsets
__device__ int  g_cur[N2];     // block-LOCAL cursors
__device__ int  g_bsum[256];
__device__ int  g_boff[256];   // per-1024-block global bases
__device__ int2 g_pairs[2 * NNZV];   // (col, val bits)

// packed f32x2 FMA (sm_103a; PTX-only path -> FFMA2)
__device__ __forceinline__ void fma_f32x2(unsigned long long& acc,
                                          unsigned long long x,
                                          unsigned long long v) {
    asm("fma.rn.f32x2 %0, %1, %2, %3;" : "=l"(acc) : "l"(x), "l"(v), "l"(acc));
}
__device__ __forceinline__ unsigned long long pack2(float lo, float hi) {
    unsigned long long r;
    asm("mov.b64 %0, {%1, %2};" : "=l"(r) : "f"(lo), "f"(hi));
    return r;
}

// ---- pass 0: zero counters ----
__global__ void k_zero(void) {
    int i = blockIdx.x * blockDim.x + threadIdx.x;
    if (i < N2) g_cnt[i] = 0;
}

// ---- pass 1: histogram of rows (both matrices fused) ----
__global__ void k_hist(const int* __restrict__ urows, const int* __restrict__ irows) {
    int idx = blockIdx.x * blockDim.x + threadIdx.x;
    if (idx < NNZV) {
        atomicAdd(&g_cnt[urows[idx]], 1);
    } else if (idx < 2 * NNZV) {
        atomicAdd(&g_cnt[NU + irows[idx - NNZV]], 1);
    }
}

// warp-shuffle inclusive scan helper
__device__ __forceinline__ int warp_incl_scan(int x, int lane) {
    #pragma unroll
    for (int d = 1; d < 32; d <<= 1) {
        int t = __shfl_up_sync(0xFFFFFFFFu, x, d);
        if (lane >= d) x += t;
    }
    return x;
}

// ---- pass 2a: per-block exclusive scan of counts; also init local cursors ----
__global__ void k_scan1(void) {
    int i    = blockIdx.x * 1024 + threadIdx.x;
    int lane = threadIdx.x & 31;
    int w    = threadIdx.x >> 5;
    int v    = (i < N2) ? g_cnt[i] : 0;

    int x = warp_incl_scan(v, lane);

    __shared__ int ws[32];
    if (lane == 31) ws[w] = x;
    __syncthreads();
    if (w == 0) {
        int y = ws[lane];
        y = warp_incl_scan(y, lane);
        ws[lane] = y;
    }
    __syncthreads();
    int base = (w > 0) ? ws[w - 1] : 0;
    if (i < N2) {
        int o = base + x - v;          // block-local exclusive
        g_off[i] = o;
        g_cur[i] = o;
    }
    if (threadIdx.x == 1023) g_bsum[blockIdx.x] = base + x;  // block total
}

// ---- pass 2b: scan the 196 block sums (single block, 256 threads) ----
__global__ void k_scan2(void) {
    int i    = threadIdx.x;
    int lane = i & 31;
    int w    = i >> 5;
    int v    = (i < NBLK) ? g_bsum[i] : 0;

    int x = warp_incl_scan(v, lane);

    __shared__ int ws[8];
    if (lane == 31) ws[w] = x;
    __syncthreads();
    if (w == 0) {
        int y = (lane < 8) ? ws[lane] : 0;
        y = warp_incl_scan(y, lane);
        if (lane < 8) ws[lane] = y;
    }
    __syncthreads();
    int base = (w > 0) ? ws[w - 1] : 0;
    if (i < 256) g_boff[i] = base + x - v;
}

// ---- pass 3: scatter (col,val) into row-grouped order (one 8B store/nnz) ----
__global__ void k_scatter(const int*   __restrict__ urows, const int* __restrict__ ucols,
                          const float* __restrict__ uvals,
                          const int*   __restrict__ irows, const int* __restrict__ icols,
                          const float* __restrict__ ivals) {
    int idx = blockIdx.x * blockDim.x + threadIdx.x;
    int r, c;
    float v;
    if (idx < NNZV) {
        r = urows[idx];
        c = ucols[idx];              // users_emb = dense rows [0, NU)
        v = uvals[idx];
    } else if (idx < 2 * NNZV) {
        int j = idx - NNZV;
        r = NU + irows[j];
        c = NU + icols[j];           // items_emb = dense rows [NU, NU+NI)
        v = ivals[j];
    } else {
        return;
    }
    int pos = atomicAdd(&g_cur[r], 1) + g_boff[r >> 10];
    g_pairs[pos] = make_int2(c, __float_as_int(v));
}

// ---- pass 4: one warp per row; uniform pair broadcast, FFMA2 math ----
__global__ void k_accum(const ulonglong2* __restrict__ in2,   // 32 x 16B per row
                        float4* __restrict__ out4) {
    int warp = (blockIdx.x * blockDim.x + threadIdx.x) >> 5;
    int lane = threadIdx.x & 31;
    if (warp >= N2) return;

    int s = g_off[warp] + g_boff[warp >> 10];
    int e = s + g_cnt[warp];

    unsigned long long a01 = 0ull, a23 = 0ull;   // two packed f32x2 accumulators

    int j = s;
    // unroll-by-2: two independent uniform pair loads + gathers in flight
    for (; j + 2 <= e; j += 2) {
        int2 p0 = g_pairs[j];         // uniform across warp -> L1 broadcast
        int2 p1 = g_pairs[j + 1];
        ulonglong2 x0 = in2[(size_t)p0.x * 32 + lane];
        ulonglong2 x1 = in2[(size_t)p1.x * 32 + lane];
        float v0 = __int_as_float(p0.y);
        float v1 = __int_as_float(p1.y);
        unsigned long long vv0 = pack2(v0, v0);
        unsigned long long vv1 = pack2(v1, v1);
        fma_f32x2(a01, x0.x, vv0);
        fma_f32x2(a23, x0.y, vv0);
        fma_f32x2(a01, x1.x, vv1);
        fma_f32x2(a23, x1.y, vv1);
    }
    if (j < e) {
        int2 p0 = g_pairs[j];
        ulonglong2 x0 = in2[(size_t)p0.x * 32 + lane];
        float v0 = __int_as_float(p0.y);
        unsigned long long vv0 = pack2(v0, v0);
        fma_f32x2(a01, x0.x, vv0);
        fma_f32x2(a23, x0.y, vv0);
    }

    float4 r;
    asm("mov.b64 {%0, %1}, %2;" : "=f"(r.x), "=f"(r.y) : "l"(a01));
    asm("mov.b64 {%0, %1}, %2;" : "=f"(r.z), "=f"(r.w) : "l"(a23));
    out4[(size_t)warp * 32 + lane] = r;
}

extern "C" void kernel_launch(void* const* d_in, const int* in_sizes, int n_in,
                              void* d_out, int out_size) {
    const float* input = (const float*)d_in[0];
    const int*   urows = (const int*)  d_in[1];
    const int*   ucols = (const int*)  d_in[2];
    const float* uvals = (const float*)d_in[3];
    const int*   irows = (const int*)  d_in[4];
    const int*   icols = (const int*)  d_in[5];
    const float* ivals = (const float*)d_in[6];
    float* out = (float*)d_out;

    (void)in_sizes; (void)n_in; (void)out_size;

    k_zero   <<<(N2 + 255) / 256, 256>>>();
    k_hist   <<<(2 * NNZV + 255) / 256, 256>>>(urows, irows);
    k_scan1  <<<NBLK, 1024>>>();
    k_scan2  <<<1, 256>>>();
    k_scatter<<<(2 * NNZV + 255) / 256, 256>>>(urows, ucols, uvals, irows, icols, ivals);
    k_accum  <<<(N2 * 32 + 255) / 256, 256>>>((const ulonglong2*)input, (float4*)out);
}

// round 15
// speedup vs baseline: 1.2350x; 1.2350x over previous
#include <cuda_runtime.h>

#define NU   100000
#define NI   100000
#define N2   200000            // total output rows (users + items)
#define NNZV 3200000
#define D    128
#define NBLK 196               // ceil(N2/1024)

// ---- static scratch (no allocations allowed) ----
__device__ int  g_cnt[N2];
__device__ int  g_off[N2];     // block-LOCAL exclusive offsets
__device__ int  g_cur[N2];     // block-LOCAL cursors
__device__ int  g_bsum[256];
__device__ int  g_boff[256];   // per-1024-block global bases
__device__ int2 g_pairs[2 * NNZV];   // (col, val bits)

// ---- pass 0: zero counters ----
__global__ void k_zero(void) {
    int i = blockIdx.x * blockDim.x + threadIdx.x;
    if (i < N2) g_cnt[i] = 0;
}

// ---- pass 1: histogram of rows (both matrices fused) ----
__global__ void k_hist(const int* __restrict__ urows, const int* __restrict__ irows) {
    int idx = blockIdx.x * blockDim.x + threadIdx.x;
    if (idx < NNZV) {
        atomicAdd(&g_cnt[urows[idx]], 1);
    } else if (idx < 2 * NNZV) {
        atomicAdd(&g_cnt[NU + irows[idx - NNZV]], 1);
    }
}

// warp-shuffle inclusive scan helper
__device__ __forceinline__ int warp_incl_scan(int x, int lane) {
    #pragma unroll
    for (int d = 1; d < 32; d <<= 1) {
        int t = __shfl_up_sync(0xFFFFFFFFu, x, d);
        if (lane >= d) x += t;
    }
    return x;
}

// ---- pass 2a: per-block exclusive scan of counts; also init local cursors ----
__global__ void k_scan1(void) {
    int i    = blockIdx.x * 1024 + threadIdx.x;
    int lane = threadIdx.x & 31;
    int w    = threadIdx.x >> 5;
    int v    = (i < N2) ? g_cnt[i] : 0;

    int x = warp_incl_scan(v, lane);

    __shared__ int ws[32];
    if (lane == 31) ws[w] = x;
    __syncthreads();
    if (w == 0) {
        int y = ws[lane];
        y = warp_incl_scan(y, lane);
        ws[lane] = y;
    }
    __syncthreads();
    int base = (w > 0) ? ws[w - 1] : 0;
    if (i < N2) {
        int o = base + x - v;          // block-local exclusive
        g_off[i] = o;
        g_cur[i] = o;
    }
    if (threadIdx.x == 1023) g_bsum[blockIdx.x] = base + x;  // block total
}

// ---- pass 2b: scan the 196 block sums (single block, 256 threads) ----
__global__ void k_scan2(void) {
    int i    = threadIdx.x;
    int lane = i & 31;
    int w    = i >> 5;
    int v    = (i < NBLK) ? g_bsum[i] : 0;

    int x = warp_incl_scan(v, lane);

    __shared__ int ws[8];
    if (lane == 31) ws[w] = x;
    __syncthreads();
    if (w == 0) {
        int y = (lane < 8) ? ws[lane] : 0;
        y = warp_incl_scan(y, lane);
        if (lane < 8) ws[lane] = y;
    }
    __syncthreads();
    int base = (w > 0) ? ws[w - 1] : 0;
    if (i < 256) g_boff[i] = base + x - v;
}

// ---- pass 3: scatter (col,val) into row-grouped order (one 8B store/nnz) ----
__global__ void k_scatter(const int*   __restrict__ urows, const int* __restrict__ ucols,
                          const float* __restrict__ uvals,
                          const int*   __restrict__ irows, const int* __restrict__ icols,
                          const float* __restrict__ ivals) {
    int idx = blockIdx.x * blockDim.x + threadIdx.x;
    int r, c;
    float v;
    if (idx < NNZV) {
        r = urows[idx];
        c = ucols[idx];              // users_emb = dense rows [0, NU)
        v = uvals[idx];
    } else if (idx < 2 * NNZV) {
        int j = idx - NNZV;
        r = NU + irows[j];
        c = NU + icols[j];           // items_emb = dense rows [NU, NU+NI)
        v = ivals[j];
    } else {
        return;
    }
    int pos = atomicAdd(&g_cur[r], 1) + g_boff[r >> 10];
    g_pairs[pos] = make_int2(c, __float_as_int(v));
}

// ---- pass 4: one warp per output row, register accumulation, single write ----
// (R3 champion loop, verbatim: coalesced 32-wide pair load, SHFL broadcast,
//  32 independent LDG.128 gathers pipelined per batch)
__global__ void k_accum(const float4* __restrict__ in4, float4* __restrict__ out4) {
    int warp = (blockIdx.x * blockDim.x + threadIdx.x) >> 5;
    int lane = threadIdx.x & 31;
    if (warp >= N2) return;

    int s = g_off[warp] + g_boff[warp >> 10];
    int e = s + g_cnt[warp];

    float4 a = make_float4(0.f, 0.f, 0.f, 0.f);

    for (int j0 = s; j0 < e; j0 += 32) {
        int jj = j0 + lane;
        int2 p  = (jj < e) ? g_pairs[jj] : make_int2(0, 0);
        int m = e - j0;
        if (m > 32) m = 32;
        for (int k = 0; k < m; k++) {
            int   ck = __shfl_sync(0xFFFFFFFFu, p.x, k);
            float vk = __int_as_float(__shfl_sync(0xFFFFFFFFu, p.y, k));
            float4 x = in4[(size_t)ck * 32 + lane];
            a.x = fmaf(x.x, vk, a.x);
            a.y = fmaf(x.y, vk, a.y);
            a.z = fmaf(x.z, vk, a.z);
            a.w = fmaf(x.w, vk, a.w);
        }
    }
    out4[(size_t)warp * 32 + lane] = a;
}

extern "C" void kernel_launch(void* const* d_in, const int* in_sizes, int n_in,
                              void* d_out, int out_size) {
    const float* input = (const float*)d_in[0];
    const int*   urows = (const int*)  d_in[1];
    const int*   ucols = (const int*)  d_in[2];
    const float* uvals = (const float*)d_in[3];
    const int*   irows = (const int*)  d_in[4];
    const int*   icols = (const int*)  d_in[5];
    const float* ivals = (const float*)d_in[6];
    float* out = (float*)d_out;

    (void)in_sizes; (void)n_in; (void)out_size;

    k_zero   <<<(N2 + 255) / 256, 256>>>();
    k_hist   <<<(2 * NNZV + 255) / 256, 256>>>(urows, irows);
    k_scan1  <<<NBLK, 1024>>>();
    k_scan2  <<<1, 256>>>();
    k_scatter<<<(2 * NNZV + 255) / 256, 256>>>(urows, ucols, uvals, irows, icols, ivals);
    k_accum  <<<(N2 * 32 + 255) / 256, 256>>>((const float4*)input, (float4*)out);
}